// round 7
// baseline (speedup 1.0000x reference)
#include <cuda_runtime.h>
#include <math.h>

#define BS   8
#define HW   1024
#define STEP 20
#define NS   51            // hw // STEP
#define NP   512           // model points
#define NBLK (BS * NS)     // 408 hypotheses
#define NH   2             // candidate halves per hypothesis
#define NCAND (NP / NH)    // 256 candidates per CTA
#define NPAIRL (NCAND / 2) // 128 packed pairs per CTA
#define NT   128           // threads per block
#define Q    4             // query points per thread (covers all 512 queries)
#define SCORING_WEIGHT 0.01f

// Scratch (no allocations allowed)
__device__ float    g_min[NBLK][NH][NP];  // pn + partial min per (hyp, half, query)
__device__ unsigned g_hcount[NBLK];        // per-hypothesis arrival counter (self-resetting)
__device__ float    g_part[NBLK];
__device__ unsigned g_count = 0;           // global counter (self-resetting)

// ---------------------------------------------------------------------------
// Grid = 816: CTA (h, hf) scans candidate half hf (256 GT points) against all
// 512 query points of hypothesis h. GT half packed in shared as pairs
// [x0,x1, y0,y1, z0,z1, w0,w1], (x,y,z) = -2*g, w = |g|^2.
// Inner iter: 2x LDS.128 (broadcast) + 12x fma.rn.f32x2 + 8x FMNMX
// for 2 candidates x 4 queries. Second CTA of each hypothesis combines the
// halves; last combiner reduces the 408 partials.
// ---------------------------------------------------------------------------
__global__ __launch_bounds__(NT, 6) void fused_kernel(
    const float* __restrict__ pred_r,
    const float* __restrict__ pred_t,
    const float* __restrict__ pred_s,
    const float* __restrict__ gt_r,
    const float* __restrict__ gt_t,
    const float* __restrict__ model,
    float* __restrict__ out)
{
    __shared__ float sg[NPAIRL * 8];   // 4 KB packed GT half
    __shared__ float red[NT];
    __shared__ bool  s_lasth, s_lastg;

    int bx  = blockIdx.x;
    int h   = bx >> 1;          // hypothesis id
    int hf  = bx & 1;           // candidate half
    int b   = h / NS;
    int pix = (h % NS) * STEP;
    int tid = threadIdx.x;

    const float* m = model + b * 3 * NP;

    // ---- GT: build this CTA's 256 candidates (2 per thread) ----
    {
        const float* R = gt_r + b * 9;
        const float* T = gt_t + b * 3;
        float R0 = R[0], R1 = R[1], R2 = R[2];
        float R3 = R[3], R4 = R[4], R5 = R[5];
        float R6 = R[6], R7 = R[7], R8 = R[8];
        float T0 = T[0], T1 = T[1], T2 = T[2];
#pragma unroll
        for (int k = 0; k < 2; k++) {
            int l = tid + k * NT;            // local candidate 0..255
            int c = hf * NCAND + l;          // global candidate
            float vx = m[c], vy = m[NP + c], vz = m[2 * NP + c];
            float gx = fmaf(R0, vx, fmaf(R1, vy, fmaf(R2, vz, T0)));
            float gy = fmaf(R3, vx, fmaf(R4, vy, fmaf(R5, vz, T1)));
            float gz = fmaf(R6, vx, fmaf(R7, vy, fmaf(R8, vz, T2)));
            float gn = fmaf(gx, gx, fmaf(gy, gy, gz * gz));
            float* dst = sg + 8 * (l >> 1) + (l & 1);
            dst[0] = -2.0f * gx;
            dst[2] = -2.0f * gy;
            dst[4] = -2.0f * gz;
            dst[6] = gn;
        }
    }

    // ---- pose (tiny, redundant per thread; identical across both halves) ----
    const float* pr = pred_r + b * 4 * HW + pix;
    float q0 = pr[0], q1 = pr[HW], q2 = pr[2 * HW], q3 = pr[3 * HW];
    float inv = rsqrtf(q0 * q0 + q1 * q1 + q2 * q2 + q3 * q3);
    q0 *= inv; q1 *= inv; q2 *= inv; q3 *= inv;

    float R00 = 1.0f - 2.0f * (q2 * q2 + q3 * q3);
    float R01 = 2.0f * (q1 * q2 - q0 * q3);
    float R02 = 2.0f * (q0 * q2 + q1 * q3);
    float R10 = 2.0f * (q1 * q2 + q3 * q0);
    float R11 = 1.0f - 2.0f * (q1 * q1 + q3 * q3);
    float R12 = 2.0f * (q2 * q3 - q0 * q1);
    float R20 = 2.0f * (q1 * q3 - q0 * q2);
    float R21 = 2.0f * (q0 * q1 + q2 * q3);
    float R22 = 1.0f - 2.0f * (q1 * q1 + q2 * q2);

    const float* pt = pred_t + b * 3 * HW + pix;
    float tx = pt[0], ty = pt[HW], tz = pt[2 * HW];

    // ---- transform this thread's 4 query points, pack f32x2 broadcasts ----
    unsigned long long px2[Q], py2[Q], pz2[Q];
    float pn[Q];
#pragma unroll
    for (int k = 0; k < Q; k++) {
        int p = tid + k * NT;
        float vx = m[p], vy = m[NP + p], vz = m[2 * NP + p];
        float px = fmaf(R00, vx, fmaf(R01, vy, fmaf(R02, vz, tx)));
        float py = fmaf(R10, vx, fmaf(R11, vy, fmaf(R12, vz, ty)));
        float pz = fmaf(R20, vx, fmaf(R21, vy, fmaf(R22, vz, tz)));
        pn[k] = fmaf(px, px, fmaf(py, py, pz * pz));
        unsigned ux = __float_as_uint(px), uy = __float_as_uint(py), uz = __float_as_uint(pz);
        asm("mov.b64 %0, {%1, %1};" : "=l"(px2[k]) : "r"(ux));
        asm("mov.b64 %0, {%1, %1};" : "=l"(py2[k]) : "r"(uy));
        asm("mov.b64 %0, {%1, %1};" : "=l"(pz2[k]) : "r"(uz));
    }

    __syncthreads();

    // ---- scan this half's 128 candidate pairs ----
    const ulonglong2* __restrict__ sp = (const ulonglong2*)sg;
    float mn0[Q], mn1[Q];
#pragma unroll
    for (int k = 0; k < Q; k++) { mn0[k] = 3.0e38f; mn1[k] = 3.0e38f; }

#pragma unroll 4
    for (int i = 0; i < NPAIRL; i++) {
        ulonglong2 a = sp[2 * i];       // {x0,x1}, {y0,y1}
        ulonglong2 c = sp[2 * i + 1];   // {z0,z1}, {w0,w1}
#pragma unroll
        for (int k = 0; k < Q; k++) {
            unsigned long long v;
            asm("fma.rn.f32x2 %0, %1, %2, %3;" : "=l"(v) : "l"(pz2[k]), "l"(c.x), "l"(c.y));
            asm("fma.rn.f32x2 %0, %1, %2, %3;" : "=l"(v) : "l"(py2[k]), "l"(a.y), "l"(v));
            asm("fma.rn.f32x2 %0, %1, %2, %3;" : "=l"(v) : "l"(px2[k]), "l"(a.x), "l"(v));
            float v0 = __uint_as_float((unsigned)v);
            float v1 = __uint_as_float((unsigned)(v >> 32));
            mn0[k] = fminf(mn0[k], v0);
            mn1[k] = fminf(mn1[k], v1);
        }
    }

    // ---- per-query partial result: pn + min over this half ----
    float myv[Q];
#pragma unroll
    for (int k = 0; k < Q; k++) {
        myv[k] = pn[k] + fminf(mn0[k], mn1[k]);
        g_min[h][hf][tid + k * NT] = myv[k];
    }

    // ---- per-hypothesis rendezvous: second arrival combines ----
    __threadfence();
    __syncthreads();
    if (tid == 0) {
        unsigned old = atomicAdd(&g_hcount[h], 1u);
        s_lasth = (old == 1);
        if (s_lasth) g_hcount[h] = 0;   // reset for next launch
    }
    __syncthreads();
    if (!s_lasth) return;

    __threadfence();   // acquire side: order reads after observing the count

    float acc = 0.0f;
#pragma unroll
    for (int k = 0; k < Q; k++) {
        float o  = __ldcg(&g_min[h][1 - hf][tid + k * NT]);
        float m2 = fminf(myv[k], o);
        acc += sqrtf(fmaxf(m2, 0.0f));
    }

    red[tid] = acc;
    __syncthreads();
    if (tid < 64) red[tid] += red[tid + 64];
    __syncthreads();
    if (tid < 32) {
        float v = red[tid] + red[tid + 32];
#pragma unroll
        for (int o = 16; o > 0; o >>= 1)
            v += __shfl_down_sync(0xFFFFFFFFu, v, o);
        if (tid == 0) {
            float add = v * (1.0f / NP);
            float sc  = pred_s[b * HW + pix];
            g_part[h] = (add * sc - SCORING_WEIGHT * logf(sc)) * (1.0f / NBLK);
            __threadfence();
            unsigned old = atomicAdd(&g_count, 1u);
            s_lastg = (old == NBLK - 1);
        }
    }
    __syncthreads();

    // ---- last combiner: reduce 408 partials + inf/nan guard ----
    if (s_lastg && tid < 32) {
        __threadfence();
        float v = 0.0f;
        for (int i = tid; i < NBLK; i += 32) v += __ldcg(&g_part[i]);
#pragma unroll
        for (int o = 16; o > 0; o >>= 1)
            v += __shfl_down_sync(0xFFFFFFFFu, v, o);
        if (tid == 0) {
            if (isinf(v) || isnan(v)) v = 0.0f;
            out[0] = v;
            g_count = 0;   // reset for next launch / graph replay
        }
    }
}

// ---------------------------------------------------------------------------
// Inputs (metadata order): pred_r, pred_t, pred_s, mask, gt_r, gt_t,
//                          model_xyz, cls_ids
// ---------------------------------------------------------------------------
extern "C" void kernel_launch(void* const* d_in, const int* in_sizes, int n_in,
                              void* d_out, int out_size)
{
    const float* pred_r = (const float*)d_in[0];
    const float* pred_t = (const float*)d_in[1];
    const float* pred_s = (const float*)d_in[2];
    // d_in[3] = mask (unused)
    const float* gt_r   = (const float*)d_in[4];
    const float* gt_t   = (const float*)d_in[5];
    const float* model  = (const float*)d_in[6];
    // d_in[7] = cls_ids (unused)

    fused_kernel<<<NBLK * NH, NT>>>(pred_r, pred_t, pred_s, gt_r, gt_t, model,
                                    (float*)d_out);
}

// round 8
// speedup vs baseline: 1.0737x; 1.0737x over previous
#include <cuda_runtime.h>
#include <math.h>

#define BS   8
#define HW   1024
#define STEP 20
#define NS   51            // hw // STEP
#define NP   512           // model points
#define NPAIR (NP / 2)     // 256 packed GT pairs
#define NBLK (BS * NS)     // 408 hypotheses
#define NT   256           // threads per block
#define NGP  4             // candidate groups
#define NG   64            // threads per group
#define NPG  (NPAIR / NGP) // 64 pairs scanned per group
#define Q    8             // query points per thread (NG * Q = 512)
#define SCORING_WEIGHT 0.01f

// Scratch (no allocations allowed)
__device__ float    g_part[NBLK];
__device__ unsigned g_count = 0;   // last-block-done counter; self-resetting

// ---------------------------------------------------------------------------
// One block per (batch, sample) hypothesis. 256 threads in 4 candidate-groups
// of 64: group g scans GT pairs [g*64, g*64+64) against ALL 512 queries
// (thread owns Q=8 queries: gtid + k*64). GT packed in shared as pairs
// [x0,x1, y0,y1, z0,z1, w0,w1], (x,y,z) = -2*g, w = |g|^2.
// Inner iter: 2x LDS.128 (broadcast) + 24x fma.rn.f32x2 + 16x FMNMX for
// 2 candidates x 8 queries = 16 pairings. Group partial mins (pn folded in)
// combine via a shared float4 table; last CTA reduces the 408 partials.
// ---------------------------------------------------------------------------
__global__ __launch_bounds__(NT, 2) void fused_kernel(
    const float* __restrict__ pred_r,
    const float* __restrict__ pred_t,
    const float* __restrict__ pred_s,
    const float* __restrict__ gt_r,
    const float* __restrict__ gt_t,
    const float* __restrict__ model,
    float* __restrict__ out)
{
    __shared__ float sg[NP * 4];   // 8 KB GT pack; reused as [NP][NGP] combine table
    __shared__ float red[NT / 2];
    __shared__ bool  s_last;

    int blk  = blockIdx.x;
    int b    = blk / NS;
    int pix  = (blk % NS) * STEP;
    int tid  = threadIdx.x;
    int g    = tid >> 6;          // candidate group 0..3
    int gtid = tid & (NG - 1);    // 0..63

    const float* m = model + b * 3 * NP;

    // ---- GT: build the 512 packed candidates (2 per thread) ----
    {
        const float* R = gt_r + b * 9;
        const float* T = gt_t + b * 3;
        float R0 = R[0], R1 = R[1], R2 = R[2];
        float R3 = R[3], R4 = R[4], R5 = R[5];
        float R6 = R[6], R7 = R[7], R8 = R[8];
        float T0 = T[0], T1 = T[1], T2 = T[2];
#pragma unroll
        for (int k = 0; k < 2; k++) {
            int c = tid + k * NT;
            float vx = m[c], vy = m[NP + c], vz = m[2 * NP + c];
            float gx = fmaf(R0, vx, fmaf(R1, vy, fmaf(R2, vz, T0)));
            float gy = fmaf(R3, vx, fmaf(R4, vy, fmaf(R5, vz, T1)));
            float gz = fmaf(R6, vx, fmaf(R7, vy, fmaf(R8, vz, T2)));
            float gn = fmaf(gx, gx, fmaf(gy, gy, gz * gz));
            float* dst = sg + 8 * (c >> 1) + (c & 1);
            dst[0] = -2.0f * gx;
            dst[2] = -2.0f * gy;
            dst[4] = -2.0f * gz;
            dst[6] = gn;
        }
    }

    // ---- pose (tiny, redundant per thread) ----
    const float* pr = pred_r + b * 4 * HW + pix;
    float q0 = pr[0], q1 = pr[HW], q2 = pr[2 * HW], q3 = pr[3 * HW];
    float inv = rsqrtf(q0 * q0 + q1 * q1 + q2 * q2 + q3 * q3);
    q0 *= inv; q1 *= inv; q2 *= inv; q3 *= inv;

    float R00 = 1.0f - 2.0f * (q2 * q2 + q3 * q3);
    float R01 = 2.0f * (q1 * q2 - q0 * q3);
    float R02 = 2.0f * (q0 * q2 + q1 * q3);
    float R10 = 2.0f * (q1 * q2 + q3 * q0);
    float R11 = 1.0f - 2.0f * (q1 * q1 + q3 * q3);
    float R12 = 2.0f * (q2 * q3 - q0 * q1);
    float R20 = 2.0f * (q1 * q3 - q0 * q2);
    float R21 = 2.0f * (q0 * q1 + q2 * q3);
    float R22 = 1.0f - 2.0f * (q1 * q1 + q2 * q2);

    const float* pt = pred_t + b * 3 * HW + pix;
    float tx = pt[0], ty = pt[HW], tz = pt[2 * HW];

    // ---- transform this thread's Q=8 queries, pack f32x2 broadcasts ----
    unsigned long long px2[Q], py2[Q], pz2[Q];
    float pn[Q];
#pragma unroll
    for (int k = 0; k < Q; k++) {
        int p = gtid + k * NG;
        float vx = m[p], vy = m[NP + p], vz = m[2 * NP + p];
        float px = fmaf(R00, vx, fmaf(R01, vy, fmaf(R02, vz, tx)));
        float py = fmaf(R10, vx, fmaf(R11, vy, fmaf(R12, vz, ty)));
        float pz = fmaf(R20, vx, fmaf(R21, vy, fmaf(R22, vz, tz)));
        pn[k] = fmaf(px, px, fmaf(py, py, pz * pz));
        unsigned ux = __float_as_uint(px), uy = __float_as_uint(py), uz = __float_as_uint(pz);
        asm("mov.b64 %0, {%1, %1};" : "=l"(px2[k]) : "r"(ux));
        asm("mov.b64 %0, {%1, %1};" : "=l"(py2[k]) : "r"(uy));
        asm("mov.b64 %0, {%1, %1};" : "=l"(pz2[k]) : "r"(uz));
    }

    __syncthreads();

    // ---- scan this group's 64 candidate pairs against 8 queries ----
    const ulonglong2* __restrict__ sp = (const ulonglong2*)sg + g * NPG * 2;
    float mn0[Q], mn1[Q];
#pragma unroll
    for (int k = 0; k < Q; k++) { mn0[k] = 3.0e38f; mn1[k] = 3.0e38f; }

#pragma unroll 4
    for (int i = 0; i < NPG; i++) {
        ulonglong2 a = sp[2 * i];       // {x0,x1}, {y0,y1}
        ulonglong2 c = sp[2 * i + 1];   // {z0,z1}, {w0,w1}
#pragma unroll
        for (int k = 0; k < Q; k++) {
            unsigned long long v;
            asm("fma.rn.f32x2 %0, %1, %2, %3;" : "=l"(v) : "l"(pz2[k]), "l"(c.x), "l"(c.y));
            asm("fma.rn.f32x2 %0, %1, %2, %3;" : "=l"(v) : "l"(py2[k]), "l"(a.y), "l"(v));
            asm("fma.rn.f32x2 %0, %1, %2, %3;" : "=l"(v) : "l"(px2[k]), "l"(a.x), "l"(v));
            float v0 = __uint_as_float((unsigned)v);
            float v1 = __uint_as_float((unsigned)(v >> 32));
            mn0[k] = fminf(mn0[k], v0);
            mn1[k] = fminf(mn1[k], v1);
        }
    }

    // ---- publish pn + group-partial-min into the combine table ----
    __syncthreads();                       // all groups done reading sg
#pragma unroll
    for (int k = 0; k < Q; k++) {
        int p = gtid + k * NG;
        sg[p * NGP + g] = pn[k] + fminf(mn0[k], mn1[k]);
    }
    __syncthreads();

    // ---- combine: threads 0..127 each finish 4 queries ----
    if (tid < NT / 2) {
        float acc = 0.0f;
#pragma unroll
        for (int j = 0; j < 4; j++) {
            int p = tid + j * (NT / 2);
            float4 v = *(const float4*)(sg + p * NGP);
            float m2 = fminf(fminf(v.x, v.y), fminf(v.z, v.w));
            acc += sqrtf(fmaxf(m2, 0.0f));
        }
        red[tid] = acc;
    }
    __syncthreads();

    if (tid < 64) red[tid] += red[tid + 64];
    __syncthreads();
    if (tid < 32) {
        float v = red[tid] + red[tid + 32];
#pragma unroll
        for (int o = 16; o > 0; o >>= 1)
            v += __shfl_down_sync(0xFFFFFFFFu, v, o);
        if (tid == 0) {
            float add = v * (1.0f / NP);
            float sc  = pred_s[b * HW + pix];
            g_part[blk] = (add * sc - SCORING_WEIGHT * logf(sc)) * (1.0f / NBLK);
            __threadfence();
            unsigned old = atomicAdd(&g_count, 1u);
            s_last = (old == NBLK - 1);
        }
    }
    __syncthreads();

    // ---- last CTA: reduce 408 partials + inf/nan guard ----
    if (s_last && tid < 32) {
        __threadfence();
        float v = 0.0f;
        for (int i = tid; i < NBLK; i += 32) v += __ldcg(&g_part[i]);
#pragma unroll
        for (int o = 16; o > 0; o >>= 1)
            v += __shfl_down_sync(0xFFFFFFFFu, v, o);
        if (tid == 0) {
            if (isinf(v) || isnan(v)) v = 0.0f;
            out[0] = v;
            g_count = 0;   // reset for next launch / graph replay
        }
    }
}

// ---------------------------------------------------------------------------
// Inputs (metadata order): pred_r, pred_t, pred_s, mask, gt_r, gt_t,
//                          model_xyz, cls_ids
// ---------------------------------------------------------------------------
extern "C" void kernel_launch(void* const* d_in, const int* in_sizes, int n_in,
                              void* d_out, int out_size)
{
    const float* pred_r = (const float*)d_in[0];
    const float* pred_t = (const float*)d_in[1];
    const float* pred_s = (const float*)d_in[2];
    // d_in[3] = mask (unused)
    const float* gt_r   = (const float*)d_in[4];
    const float* gt_t   = (const float*)d_in[5];
    const float* model  = (const float*)d_in[6];
    // d_in[7] = cls_ids (unused)

    fused_kernel<<<NBLK, NT>>>(pred_r, pred_t, pred_s, gt_r, gt_t, model,
                               (float*)d_out);
}

// round 9
// speedup vs baseline: 1.1007x; 1.0252x over previous
#include <cuda_runtime.h>
#include <math.h>

#define BS   8
#define HW   1024
#define STEP 20
#define NS   51            // hw // STEP
#define NP   512           // model points
#define NPAIR (NP / 2)     // 256 packed GT pairs
#define NBLK (BS * NS)     // 408 hypotheses
#define NT   512           // threads per block
#define NGP  4             // candidate groups
#define NG   128           // threads per group
#define NPG  (NPAIR / NGP) // 64 pairs scanned per group
#define Q    4             // query points per thread (NG * Q = 512)
#define SCORING_WEIGHT 0.01f

// Scratch (no allocations allowed)
__device__ float    g_part[NBLK];
__device__ unsigned g_count = 0;   // last-block-done counter; self-resetting

// ---------------------------------------------------------------------------
// One block per (batch, sample) hypothesis. 512 threads in 4 candidate-groups
// of 128: group g scans GT pairs [g*64, (g+1)*64) against all 512 queries
// (thread owns Q=4 queries: gtid + k*128). GT packed in shared as pairs
// [x0,x1, y0,y1, z0,z1, w0,w1], (x,y,z) = -2*g, w = |g|^2.
// Inner iter: 2x LDS.128 (broadcast) + 12x fma.rn.f32x2 + 8x FMNMX for
// 2 candidates x 4 queries. Group partial mins (pn folded in) combine via a
// shared float4 table (reusing the GT buffer); last CTA reduces 408 partials.
// ---------------------------------------------------------------------------
__global__ __launch_bounds__(NT, 2) void fused_kernel(
    const float* __restrict__ pred_r,
    const float* __restrict__ pred_t,
    const float* __restrict__ pred_s,
    const float* __restrict__ gt_r,
    const float* __restrict__ gt_t,
    const float* __restrict__ model,
    float* __restrict__ out)
{
    __shared__ float sg[NP * 4];   // 8 KB GT pack; reused as [NP][NGP] table
    __shared__ float red[NT];
    __shared__ bool  s_last;

    int blk  = blockIdx.x;
    int b    = blk / NS;
    int pix  = (blk % NS) * STEP;
    int tid  = threadIdx.x;
    int g    = tid >> 7;          // candidate group 0..3
    int gtid = tid & (NG - 1);    // 0..127

    const float* m = model + b * 3 * NP;

    // ---- GT: build the 512 packed candidates (1 per thread) ----
    {
        const float* R = gt_r + b * 9;
        const float* T = gt_t + b * 3;
        float vx = m[tid], vy = m[NP + tid], vz = m[2 * NP + tid];
        float gx = fmaf(R[0], vx, fmaf(R[1], vy, fmaf(R[2], vz, T[0])));
        float gy = fmaf(R[3], vx, fmaf(R[4], vy, fmaf(R[5], vz, T[1])));
        float gz = fmaf(R[6], vx, fmaf(R[7], vy, fmaf(R[8], vz, T[2])));
        float gn = fmaf(gx, gx, fmaf(gy, gy, gz * gz));
        float* dst = sg + 8 * (tid >> 1) + (tid & 1);
        dst[0] = -2.0f * gx;
        dst[2] = -2.0f * gy;
        dst[4] = -2.0f * gz;
        dst[6] = gn;
    }

    // ---- pose (tiny, redundant per thread) ----
    const float* pr = pred_r + b * 4 * HW + pix;
    float q0 = pr[0], q1 = pr[HW], q2 = pr[2 * HW], q3 = pr[3 * HW];
    float inv = rsqrtf(q0 * q0 + q1 * q1 + q2 * q2 + q3 * q3);
    q0 *= inv; q1 *= inv; q2 *= inv; q3 *= inv;

    float R00 = 1.0f - 2.0f * (q2 * q2 + q3 * q3);
    float R01 = 2.0f * (q1 * q2 - q0 * q3);
    float R02 = 2.0f * (q0 * q2 + q1 * q3);
    float R10 = 2.0f * (q1 * q2 + q3 * q0);
    float R11 = 1.0f - 2.0f * (q1 * q1 + q3 * q3);
    float R12 = 2.0f * (q2 * q3 - q0 * q1);
    float R20 = 2.0f * (q1 * q3 - q0 * q2);
    float R21 = 2.0f * (q0 * q1 + q2 * q3);
    float R22 = 1.0f - 2.0f * (q1 * q1 + q2 * q2);

    const float* pt = pred_t + b * 3 * HW + pix;
    float tx = pt[0], ty = pt[HW], tz = pt[2 * HW];

    // ---- transform this thread's Q=4 queries, pack f32x2 broadcasts ----
    unsigned long long px2[Q], py2[Q], pz2[Q];
    float pn[Q];
#pragma unroll
    for (int k = 0; k < Q; k++) {
        int p = gtid + k * NG;
        float vx = m[p], vy = m[NP + p], vz = m[2 * NP + p];
        float px = fmaf(R00, vx, fmaf(R01, vy, fmaf(R02, vz, tx)));
        float py = fmaf(R10, vx, fmaf(R11, vy, fmaf(R12, vz, ty)));
        float pz = fmaf(R20, vx, fmaf(R21, vy, fmaf(R22, vz, tz)));
        pn[k] = fmaf(px, px, fmaf(py, py, pz * pz));
        unsigned ux = __float_as_uint(px), uy = __float_as_uint(py), uz = __float_as_uint(pz);
        asm("mov.b64 %0, {%1, %1};" : "=l"(px2[k]) : "r"(ux));
        asm("mov.b64 %0, {%1, %1};" : "=l"(py2[k]) : "r"(uy));
        asm("mov.b64 %0, {%1, %1};" : "=l"(pz2[k]) : "r"(uz));
    }

    __syncthreads();

    // ---- scan this group's 64 candidate pairs against 4 queries ----
    const ulonglong2* __restrict__ sp = (const ulonglong2*)sg + g * NPG * 2;
    float mn0[Q], mn1[Q];
#pragma unroll
    for (int k = 0; k < Q; k++) { mn0[k] = 3.0e38f; mn1[k] = 3.0e38f; }

#pragma unroll 4
    for (int i = 0; i < NPG; i++) {
        ulonglong2 a = sp[2 * i];       // {x0,x1}, {y0,y1}
        ulonglong2 c = sp[2 * i + 1];   // {z0,z1}, {w0,w1}
#pragma unroll
        for (int k = 0; k < Q; k++) {
            unsigned long long v;
            asm("fma.rn.f32x2 %0, %1, %2, %3;" : "=l"(v) : "l"(pz2[k]), "l"(c.x), "l"(c.y));
            asm("fma.rn.f32x2 %0, %1, %2, %3;" : "=l"(v) : "l"(py2[k]), "l"(a.y), "l"(v));
            asm("fma.rn.f32x2 %0, %1, %2, %3;" : "=l"(v) : "l"(px2[k]), "l"(a.x), "l"(v));
            float v0 = __uint_as_float((unsigned)v);
            float v1 = __uint_as_float((unsigned)(v >> 32));
            mn0[k] = fminf(mn0[k], v0);
            mn1[k] = fminf(mn1[k], v1);
        }
    }

    // ---- publish pn + group-partial-min into the combine table ----
    __syncthreads();                       // all groups done reading sg
#pragma unroll
    for (int k = 0; k < Q; k++) {
        int p = gtid + k * NG;
        sg[p * NGP + g] = pn[k] + fminf(mn0[k], mn1[k]);
    }
    __syncthreads();

    // ---- combine: each thread finishes 1 query ----
    {
        float4 v = *(const float4*)(sg + tid * NGP);
        float m2 = fminf(fminf(v.x, v.y), fminf(v.z, v.w));
        red[tid] = sqrtf(fmaxf(m2, 0.0f));
    }
    __syncthreads();

#pragma unroll
    for (int s = NT / 2; s >= 32; s >>= 1) {   // fold down to 32 inclusive
        if (tid < s) red[tid] += red[tid + s];
        __syncthreads();
    }
    if (tid < 32) {
        float v = red[tid];
#pragma unroll
        for (int o = 16; o > 0; o >>= 1)
            v += __shfl_down_sync(0xFFFFFFFFu, v, o);
        if (tid == 0) {
            float add = v * (1.0f / NP);
            float sc  = pred_s[b * HW + pix];
            g_part[blk] = (add * sc - SCORING_WEIGHT * logf(sc)) * (1.0f / NBLK);
            __threadfence();
            unsigned old = atomicAdd(&g_count, 1u);
            s_last = (old == NBLK - 1);
        }
    }
    __syncthreads();

    // ---- last CTA: reduce 408 partials + inf/nan guard ----
    if (s_last && tid < 32) {
        __threadfence();
        float v = 0.0f;
        for (int i = tid; i < NBLK; i += 32) v += __ldcg(&g_part[i]);
#pragma unroll
        for (int o = 16; o > 0; o >>= 1)
            v += __shfl_down_sync(0xFFFFFFFFu, v, o);
        if (tid == 0) {
            if (isinf(v) || isnan(v)) v = 0.0f;
            out[0] = v;
            g_count = 0;   // reset for next launch / graph replay
        }
    }
}

// ---------------------------------------------------------------------------
// Inputs (metadata order): pred_r, pred_t, pred_s, mask, gt_r, gt_t,
//                          model_xyz, cls_ids
// ---------------------------------------------------------------------------
extern "C" void kernel_launch(void* const* d_in, const int* in_sizes, int n_in,
                              void* d_out, int out_size)
{
    const float* pred_r = (const float*)d_in[0];
    const float* pred_t = (const float*)d_in[1];
    const float* pred_s = (const float*)d_in[2];
    // d_in[3] = mask (unused)
    const float* gt_r   = (const float*)d_in[4];
    const float* gt_t   = (const float*)d_in[5];
    const float* model  = (const float*)d_in[6];
    // d_in[7] = cls_ids (unused)

    fused_kernel<<<NBLK, NT>>>(pred_r, pred_t, pred_s, gt_r, gt_t, model,
                               (float*)d_out);
}